// round 2
// baseline (speedup 1.0000x reference)
#include <cuda_runtime.h>
#include <cuda_bf16.h>

#define T_SEQ 4096
#define C_EMB 1024
#define NH 8
#define HD 128
#define HALF 64

// Scratch (device globals: allocation-free per harness rules)
__device__ float g_q[T_SEQ * C_EMB];
__device__ float g_k[T_SEQ * C_EMB];
__device__ float g_v[T_SEQ * C_EMB];
__device__ float g_y[T_SEQ * C_EMB];

// ---------------------------------------------------------------------------
// Generic fp32 tiled GEMM: C[M,N] = A[M,K] @ B[K,N]
// BM=BN=64, BK=16, 256 threads, 4x4 accum per thread.
// Requires M%64==0, N%64==0, K%16==0 (all true here).
// ---------------------------------------------------------------------------
__global__ __launch_bounds__(256) void gemm_kernel(
    const float* __restrict__ A, const float* __restrict__ B,
    float* __restrict__ C, int M, int N, int K)
{
    __shared__ float As[16][68];   // stored [k][m], padded
    __shared__ float Bs[16][68];   // stored [k][n], padded

    int tid = threadIdx.x;
    int bm = blockIdx.y * 64;
    int bn = blockIdx.x * 64;
    int ty = tid >> 4;          // 0..15
    int tx = tid & 15;          // 0..15

    int arow = tid >> 2;            // 0..63
    int acol = (tid & 3) * 4;       // 0,4,8,12
    int brow = tid >> 4;            // 0..15
    int bcol = (tid & 15) * 4;      // 0..60

    float acc[4][4];
    #pragma unroll
    for (int i = 0; i < 4; ++i)
        #pragma unroll
        for (int j = 0; j < 4; ++j) acc[i][j] = 0.f;

    for (int k0 = 0; k0 < K; k0 += 16) {
        float4 a4 = *(const float4*)&A[(bm + arow) * K + k0 + acol];
        As[acol + 0][arow] = a4.x;
        As[acol + 1][arow] = a4.y;
        As[acol + 2][arow] = a4.z;
        As[acol + 3][arow] = a4.w;
        *(float4*)&Bs[brow][bcol] = *(const float4*)&B[(k0 + brow) * N + bn + bcol];
        __syncthreads();

        #pragma unroll
        for (int kk = 0; kk < 16; ++kk) {
            float ra[4], rb[4];
            *(float4*)ra = *(float4*)&As[kk][ty * 4];
            *(float4*)rb = *(float4*)&Bs[kk][tx * 4];
            #pragma unroll
            for (int i = 0; i < 4; ++i)
                #pragma unroll
                for (int j = 0; j < 4; ++j)
                    acc[i][j] += ra[i] * rb[j];
        }
        __syncthreads();
    }

    #pragma unroll
    for (int i = 0; i < 4; ++i) {
        float4 o = make_float4(acc[i][0], acc[i][1], acc[i][2], acc[i][3]);
        *(float4*)&C[(bm + ty * 4 + i) * N + bn + tx * 4] = o;
    }
}

// ---------------------------------------------------------------------------
// v += 2*sigmoid(x[:, :32] @ w_gate)[h] * ve     (one block per token)
// ---------------------------------------------------------------------------
__global__ __launch_bounds__(256) void gate_ve_kernel(
    const float* __restrict__ x, const float* __restrict__ ve,
    const float* __restrict__ w_gate)
{
    int t = blockIdx.x;
    __shared__ float xs[32];
    __shared__ float gate[NH];
    int tid = threadIdx.x;
    if (tid < 32) xs[tid] = x[t * C_EMB + tid];
    __syncthreads();
    if (tid < NH) {
        float s = 0.f;
        #pragma unroll
        for (int c = 0; c < 32; ++c) s += xs[c] * w_gate[c * NH + tid];
        gate[tid] = 2.f / (1.f + __expf(-s));
    }
    __syncthreads();
    for (int i = tid; i < C_EMB; i += 256)
        g_v[t * C_EMB + i] += gate[i >> 7] * ve[t * C_EMB + i];
}

// ---------------------------------------------------------------------------
// RoPE + RMSnorm on q (z=0) and k (z=1). One 64-thread block per (token, head).
// ---------------------------------------------------------------------------
__global__ __launch_bounds__(64) void rope_norm_kernel(
    const float* __restrict__ cosb, const float* __restrict__ sinb)
{
    float* buf = (blockIdx.z == 0) ? g_q : g_k;
    int t = blockIdx.x, h = blockIdx.y;
    int d = threadIdx.x; // 0..63
    float* p = buf + t * C_EMB + h * HD;

    float x1 = p[d], x2 = p[d + HALF];
    float cs = cosb[t * HALF + d], sn = sinb[t * HALF + d];
    float y1 = x1 * cs + x2 * sn;
    float y2 = -x1 * sn + x2 * cs;

    float ss = y1 * y1 + y2 * y2;
    #pragma unroll
    for (int o = 16; o; o >>= 1) ss += __shfl_xor_sync(0xffffffffu, ss, o);
    __shared__ float w2[2];
    if ((d & 31) == 0) w2[d >> 5] = ss;
    __syncthreads();
    float tot = w2[0] + w2[1];
    float r = rsqrtf(tot * (1.f / HD) + 1e-6f);
    p[d] = y1 * r;
    p[d + HALF] = y2 * r;
}

// ---------------------------------------------------------------------------
// Windowed causal flash attention.
// Block = (64 queries, 1 head), 256 threads: row = tid>>2 (0..63), c = tid&3.
// Key tiles of 32. Online softmax, O accumulated in registers (32 f/thread,
// interleaved 4-float chunks: dims c*4 + k*16).
// ---------------------------------------------------------------------------
#define QS_STRIDE 132
#define SS_STRIDE 36
#define ATTN_SMEM ((64 * QS_STRIDE + 32 * QS_STRIDE * 2 + 64 * SS_STRIDE) * 4)

__global__ __launch_bounds__(256) void attn_kernel(const int* __restrict__ winp)
{
    extern __shared__ float sm[];
    float* Qs = sm;                       // 64 x 132
    float* Ks = Qs + 64 * QS_STRIDE;      // 32 x 132
    float* Vs = Ks + 32 * QS_STRIDE;      // 32 x 132
    float* Ss = Vs + 32 * QS_STRIDE;      // 64 x 36

    int W = *winp;

    int qt = blockIdx.x, h = blockIdx.y;
    int q0 = qt * 64;
    int tid = threadIdx.x;
    int row = tid >> 2, c = tid & 3;
    int qi = q0 + row;
    const float scale = 0.08838834764831845f; // 1/sqrt(128)

    // Load Q tile (64 x 128)
    for (int i = tid; i < 64 * 32; i += 256) {
        int r = i >> 5, dd = (i & 31) << 2;
        *(float4*)&Qs[r * QS_STRIDE + dd] =
            *(const float4*)&g_q[(q0 + r) * C_EMB + h * HD + dd];
    }

    float O[8][4];
    #pragma unroll
    for (int k = 0; k < 8; ++k)
        #pragma unroll
        for (int i = 0; i < 4; ++i) O[k][i] = 0.f;
    float m = -1e30f, l = 0.f;

    int lo = q0 - W + 1; if (lo < 0) lo = 0;
    int kt0 = lo >> 5;
    int kt1 = (q0 + 63) >> 5;

    for (int kt = kt0; kt <= kt1; ++kt) {
        int kbase = kt * 32;
        // Load K/V tiles (32 x 128 each)
        for (int i = tid; i < 32 * 32; i += 256) {
            int r = i >> 5, dd = (i & 31) << 2;
            *(float4*)&Ks[r * QS_STRIDE + dd] =
                *(const float4*)&g_k[(kbase + r) * C_EMB + h * HD + dd];
            *(float4*)&Vs[r * QS_STRIDE + dd] =
                *(const float4*)&g_v[(kbase + r) * C_EMB + h * HD + dd];
        }
        __syncthreads();

        // Scores: thread handles keys j = jj*4 + c, jj in [0,8)
        float s[8];
        #pragma unroll
        for (int jj = 0; jj < 8; ++jj) s[jj] = 0.f;
        #pragma unroll 4
        for (int dd = 0; dd < HD; dd += 4) {
            float4 q4 = *(float4*)&Qs[row * QS_STRIDE + dd];
            #pragma unroll
            for (int jj = 0; jj < 8; ++jj) {
                float4 k4 = *(float4*)&Ks[(jj * 4 + c) * QS_STRIDE + dd];
                s[jj] += q4.x * k4.x + q4.y * k4.y + q4.z * k4.z + q4.w * k4.w;
            }
        }

        // Mask + row max
        float smax = -1e30f;
        #pragma unroll
        for (int jj = 0; jj < 8; ++jj) {
            int kj = kbase + jj * 4 + c;
            bool valid = (kj <= qi) && (qi - kj < W);
            s[jj] = valid ? s[jj] * scale : -1e30f;
            smax = fmaxf(smax, s[jj]);
        }
        smax = fmaxf(smax, __shfl_xor_sync(0xffffffffu, smax, 1));
        smax = fmaxf(smax, __shfl_xor_sync(0xffffffffu, smax, 2));

        float mnew = fmaxf(m, smax);
        float alpha = __expf(m - mnew);
        m = mnew;
        l *= alpha;
        #pragma unroll
        for (int k = 0; k < 8; ++k)
            #pragma unroll
            for (int i = 0; i < 4; ++i) O[k][i] *= alpha;

        float lsum = 0.f;
        #pragma unroll
        for (int jj = 0; jj < 8; ++jj) {
            float p = __expf(s[jj] - mnew);
            Ss[row * SS_STRIDE + jj * 4 + c] = p;
            lsum += p;
        }
        lsum += __shfl_xor_sync(0xffffffffu, lsum, 1);
        lsum += __shfl_xor_sync(0xffffffffu, lsum, 2);
        l += lsum;
        __syncwarp();

        // Accumulate O over all 32 keys; thread owns dims {c*4 + k*16 .. +3}
        for (int j = 0; j < 32; ++j) {
            float p = Ss[row * SS_STRIDE + j];
            const float* vr = &Vs[j * QS_STRIDE + c * 4];
            #pragma unroll
            for (int k = 0; k < 8; ++k) {
                float4 v4 = *(const float4*)&vr[k * 16];
                O[k][0] += p * v4.x;
                O[k][1] += p * v4.y;
                O[k][2] += p * v4.z;
                O[k][3] += p * v4.w;
            }
        }
        __syncthreads();
    }

    float inv = 1.f / l;
    #pragma unroll
    for (int k = 0; k < 8; ++k) {
        float4 o4 = make_float4(O[k][0] * inv, O[k][1] * inv,
                                O[k][2] * inv, O[k][3] * inv);
        *(float4*)&g_y[qi * C_EMB + h * HD + c * 4 + k * 16] = o4;
    }
}

// ---------------------------------------------------------------------------
extern "C" void kernel_launch(void* const* d_in, const int* in_sizes, int n_in,
                              void* d_out, int out_size)
{
    const float* x    = (const float*)d_in[0];
    const float* ve   = (const float*)d_in[1];
    const float* cosb = (const float*)d_in[2];
    const float* sinb = (const float*)d_in[3];
    const float* wq   = (const float*)d_in[4];
    const float* wk   = (const float*)d_in[5];
    const float* wv   = (const float*)d_in[6];
    const float* wg   = (const float*)d_in[7];
    const float* wp   = (const float*)d_in[8];
    const int*   win  = (const int*)d_in[9];
    float* out = (float*)d_out;

    float *q, *k, *v, *y;
    cudaGetSymbolAddress((void**)&q, g_q);
    cudaGetSymbolAddress((void**)&k, g_k);
    cudaGetSymbolAddress((void**)&v, g_v);
    cudaGetSymbolAddress((void**)&y, g_y);

    dim3 gg(C_EMB / 64, T_SEQ / 64);
    gemm_kernel<<<gg, 256>>>(x, wq, q, T_SEQ, C_EMB, C_EMB);
    gemm_kernel<<<gg, 256>>>(x, wk, k, T_SEQ, C_EMB, C_EMB);
    gemm_kernel<<<gg, 256>>>(x, wv, v, T_SEQ, C_EMB, C_EMB);

    gate_ve_kernel<<<T_SEQ, 256>>>(x, ve, wg);
    rope_norm_kernel<<<dim3(T_SEQ, NH, 2), 64>>>(cosb, sinb);

    cudaFuncSetAttribute(attn_kernel,
                         cudaFuncAttributeMaxDynamicSharedMemorySize, ATTN_SMEM);
    attn_kernel<<<dim3(T_SEQ / 64, NH), 256, ATTN_SMEM>>>(win);

    gemm_kernel<<<gg, 256>>>(y, wp, out, T_SEQ, C_EMB, C_EMB);
}

// round 3
// speedup vs baseline: 1.4102x; 1.4102x over previous
#include <cuda_runtime.h>
#include <cuda_bf16.h>
#include <cstdint>

#define T_SEQ 4096
#define C_EMB 1024
#define NH 8
#define HD 128
#define HALF 64

// Scratch (device globals: allocation-free per harness rules)
__device__ float g_q[T_SEQ * C_EMB];
__device__ float g_k[T_SEQ * C_EMB];
__device__ float g_v[T_SEQ * C_EMB];
__device__ float g_y[T_SEQ * C_EMB];

__device__ __forceinline__ uint32_t f2tf(float x) {
    uint32_t r;
    asm("cvt.rna.tf32.f32 %0, %1;" : "=r"(r) : "f"(x));
    return r;
}

// ---------------------------------------------------------------------------
// TF32 tensor-core GEMM: C[M,N] = A[M,K] @ B[K,N], fp32 in/out.
// BM=BN=128, BK=16, 256 threads = 8 warps (2x4), warp tile 64x32.
// mma.sync.m16n8k8 tf32. Smem strides 20 (A) / 136 (B): conflict-free frag LDS.
// Requires M%128==0, N%128==0, K%16==0 (all true here).
// ---------------------------------------------------------------------------
#define AS_STRIDE 20
#define BS_STRIDE 136

__global__ __launch_bounds__(256) void gemm_tf32_kernel(
    const float* __restrict__ A, const float* __restrict__ B,
    float* __restrict__ C, int M, int N, int K)
{
    __shared__ uint32_t As[128 * AS_STRIDE];
    __shared__ uint32_t Bs[16 * BS_STRIDE];

    int tid = threadIdx.x;
    int lane = tid & 31, warp = tid >> 5;
    int wm = (warp >> 2) * 64;   // 0, 64
    int wn = (warp & 3) * 32;    // 0, 32, 64, 96
    int bm = blockIdx.y * 128, bn = blockIdx.x * 128;

    float acc[4][4][4];
    #pragma unroll
    for (int mt = 0; mt < 4; ++mt)
        #pragma unroll
        for (int nt = 0; nt < 4; ++nt)
            #pragma unroll
            for (int i = 0; i < 4; ++i) acc[mt][nt][i] = 0.f;

    for (int k0 = 0; k0 < K; k0 += 16) {
        // A tile: 128 x 16 (512 float4s, 2 per thread)
        #pragma unroll
        for (int j = 0; j < 2; ++j) {
            int i = tid + j * 256;
            int r = i >> 2, c4 = (i & 3) << 2;
            float4 v = *(const float4*)&A[(bm + r) * K + k0 + c4];
            uint4 u = make_uint4(f2tf(v.x), f2tf(v.y), f2tf(v.z), f2tf(v.w));
            *(uint4*)&As[r * AS_STRIDE + c4] = u;
        }
        // B tile: 16 x 128 (512 float4s, 2 per thread)
        #pragma unroll
        for (int j = 0; j < 2; ++j) {
            int i = tid + j * 256;
            int r = i >> 5, c4 = (i & 31) << 2;
            float4 v = *(const float4*)&B[(k0 + r) * N + bn + c4];
            uint4 u = make_uint4(f2tf(v.x), f2tf(v.y), f2tf(v.z), f2tf(v.w));
            *(uint4*)&Bs[r * BS_STRIDE + c4] = u;
        }
        __syncthreads();

        #pragma unroll
        for (int ks = 0; ks < 2; ++ks) {
            int kb = ks * 8;
            uint32_t af[4][4];
            #pragma unroll
            for (int mt = 0; mt < 4; ++mt) {
                int r0 = wm + mt * 16 + (lane >> 2);
                int c0 = kb + (lane & 3);
                af[mt][0] = As[r0 * AS_STRIDE + c0];
                af[mt][1] = As[(r0 + 8) * AS_STRIDE + c0];
                af[mt][2] = As[r0 * AS_STRIDE + c0 + 4];
                af[mt][3] = As[(r0 + 8) * AS_STRIDE + c0 + 4];
            }
            uint32_t bf[4][2];
            #pragma unroll
            for (int nt = 0; nt < 4; ++nt) {
                int rr = kb + (lane & 3);
                int cc = wn + nt * 8 + (lane >> 2);
                bf[nt][0] = Bs[rr * BS_STRIDE + cc];
                bf[nt][1] = Bs[(rr + 4) * BS_STRIDE + cc];
            }
            #pragma unroll
            for (int mt = 0; mt < 4; ++mt)
                #pragma unroll
                for (int nt = 0; nt < 4; ++nt) {
                    asm volatile(
                        "mma.sync.aligned.m16n8k8.row.col.f32.tf32.tf32.f32 "
                        "{%0,%1,%2,%3}, {%4,%5,%6,%7}, {%8,%9}, {%0,%1,%2,%3};"
                        : "+f"(acc[mt][nt][0]), "+f"(acc[mt][nt][1]),
                          "+f"(acc[mt][nt][2]), "+f"(acc[mt][nt][3])
                        : "r"(af[mt][0]), "r"(af[mt][1]),
                          "r"(af[mt][2]), "r"(af[mt][3]),
                          "r"(bf[nt][0]), "r"(bf[nt][1]));
                }
        }
        __syncthreads();
    }

    #pragma unroll
    for (int mt = 0; mt < 4; ++mt) {
        int row = bm + wm + mt * 16 + (lane >> 2);
        #pragma unroll
        for (int nt = 0; nt < 4; ++nt) {
            int col = bn + wn + nt * 8 + ((lane & 3) << 1);
            *(float2*)&C[row * N + col] =
                make_float2(acc[mt][nt][0], acc[mt][nt][1]);
            *(float2*)&C[(row + 8) * N + col] =
                make_float2(acc[mt][nt][2], acc[mt][nt][3]);
        }
    }
}

// ---------------------------------------------------------------------------
// v += 2*sigmoid(x[:, :32] @ w_gate)[h] * ve     (one block per token)
// ---------------------------------------------------------------------------
__global__ __launch_bounds__(256) void gate_ve_kernel(
    const float* __restrict__ x, const float* __restrict__ ve,
    const float* __restrict__ w_gate)
{
    int t = blockIdx.x;
    __shared__ float xs[32];
    __shared__ float gate[NH];
    int tid = threadIdx.x;
    if (tid < 32) xs[tid] = x[t * C_EMB + tid];
    __syncthreads();
    if (tid < NH) {
        float s = 0.f;
        #pragma unroll
        for (int c = 0; c < 32; ++c) s += xs[c] * w_gate[c * NH + tid];
        gate[tid] = 2.f / (1.f + __expf(-s));
    }
    __syncthreads();
    for (int i = tid; i < C_EMB; i += 256)
        g_v[t * C_EMB + i] += gate[i >> 7] * ve[t * C_EMB + i];
}

// ---------------------------------------------------------------------------
// RoPE + RMSnorm on q (z=0) and k (z=1). One 64-thread block per (token, head).
// ---------------------------------------------------------------------------
__global__ __launch_bounds__(64) void rope_norm_kernel(
    const float* __restrict__ cosb, const float* __restrict__ sinb)
{
    float* buf = (blockIdx.z == 0) ? g_q : g_k;
    int t = blockIdx.x, h = blockIdx.y;
    int d = threadIdx.x; // 0..63
    float* p = buf + t * C_EMB + h * HD;

    float x1 = p[d], x2 = p[d + HALF];
    float cs = cosb[t * HALF + d], sn = sinb[t * HALF + d];
    float y1 = x1 * cs + x2 * sn;
    float y2 = -x1 * sn + x2 * cs;

    float ss = y1 * y1 + y2 * y2;
    #pragma unroll
    for (int o = 16; o; o >>= 1) ss += __shfl_xor_sync(0xffffffffu, ss, o);
    __shared__ float w2[2];
    if ((d & 31) == 0) w2[d >> 5] = ss;
    __syncthreads();
    float tot = w2[0] + w2[1];
    float r = rsqrtf(tot * (1.f / HD) + 1e-6f);
    p[d] = y1 * r;
    p[d + HALF] = y2 * r;
}

// ---------------------------------------------------------------------------
// Windowed causal flash attention (fp32).
// Block = (64 queries, 1 head), 256 threads: row = tid>>2, c = tid&3.
// ---------------------------------------------------------------------------
#define QS_STRIDE 132
#define SS_STRIDE 36
#define ATTN_SMEM ((64 * QS_STRIDE + 32 * QS_STRIDE * 2 + 64 * SS_STRIDE) * 4)

__global__ __launch_bounds__(256) void attn_kernel(const int* __restrict__ winp)
{
    extern __shared__ float sm[];
    float* Qs = sm;                       // 64 x 132
    float* Ks = Qs + 64 * QS_STRIDE;      // 32 x 132
    float* Vs = Ks + 32 * QS_STRIDE;      // 32 x 132
    float* Ss = Vs + 32 * QS_STRIDE;      // 64 x 36

    int W = *winp;

    int qt = blockIdx.x, h = blockIdx.y;
    int q0 = qt * 64;
    int tid = threadIdx.x;
    int row = tid >> 2, c = tid & 3;
    int qi = q0 + row;
    const float scale = 0.08838834764831845f; // 1/sqrt(128)

    for (int i = tid; i < 64 * 32; i += 256) {
        int r = i >> 5, dd = (i & 31) << 2;
        *(float4*)&Qs[r * QS_STRIDE + dd] =
            *(const float4*)&g_q[(q0 + r) * C_EMB + h * HD + dd];
    }

    float O[8][4];
    #pragma unroll
    for (int k = 0; k < 8; ++k)
        #pragma unroll
        for (int i = 0; i < 4; ++i) O[k][i] = 0.f;
    float m = -1e30f, l = 0.f;

    int lo = q0 - W + 1; if (lo < 0) lo = 0;
    int kt0 = lo >> 5;
    int kt1 = (q0 + 63) >> 5;

    for (int kt = kt0; kt <= kt1; ++kt) {
        int kbase = kt * 32;
        for (int i = tid; i < 32 * 32; i += 256) {
            int r = i >> 5, dd = (i & 31) << 2;
            *(float4*)&Ks[r * QS_STRIDE + dd] =
                *(const float4*)&g_k[(kbase + r) * C_EMB + h * HD + dd];
            *(float4*)&Vs[r * QS_STRIDE + dd] =
                *(const float4*)&g_v[(kbase + r) * C_EMB + h * HD + dd];
        }
        __syncthreads();

        float s[8];
        #pragma unroll
        for (int jj = 0; jj < 8; ++jj) s[jj] = 0.f;
        #pragma unroll 4
        for (int dd = 0; dd < HD; dd += 4) {
            float4 q4 = *(float4*)&Qs[row * QS_STRIDE + dd];
            #pragma unroll
            for (int jj = 0; jj < 8; ++jj) {
                float4 k4 = *(float4*)&Ks[(jj * 4 + c) * QS_STRIDE + dd];
                s[jj] += q4.x * k4.x + q4.y * k4.y + q4.z * k4.z + q4.w * k4.w;
            }
        }

        float smax = -1e30f;
        #pragma unroll
        for (int jj = 0; jj < 8; ++jj) {
            int kj = kbase + jj * 4 + c;
            bool valid = (kj <= qi) && (qi - kj < W);
            s[jj] = valid ? s[jj] * scale : -1e30f;
            smax = fmaxf(smax, s[jj]);
        }
        smax = fmaxf(smax, __shfl_xor_sync(0xffffffffu, smax, 1));
        smax = fmaxf(smax, __shfl_xor_sync(0xffffffffu, smax, 2));

        float mnew = fmaxf(m, smax);
        float alpha = __expf(m - mnew);
        m = mnew;
        l *= alpha;
        #pragma unroll
        for (int k = 0; k < 8; ++k)
            #pragma unroll
            for (int i = 0; i < 4; ++i) O[k][i] *= alpha;

        float lsum = 0.f;
        #pragma unroll
        for (int jj = 0; jj < 8; ++jj) {
            float p = __expf(s[jj] - mnew);
            Ss[row * SS_STRIDE + jj * 4 + c] = p;
            lsum += p;
        }
        lsum += __shfl_xor_sync(0xffffffffu, lsum, 1);
        lsum += __shfl_xor_sync(0xffffffffu, lsum, 2);
        l += lsum;
        __syncwarp();

        for (int j = 0; j < 32; ++j) {
            float p = Ss[row * SS_STRIDE + j];
            const float* vr = &Vs[j * QS_STRIDE + c * 4];
            #pragma unroll
            for (int k = 0; k < 8; ++k) {
                float4 v4 = *(const float4*)&vr[k * 16];
                O[k][0] += p * v4.x;
                O[k][1] += p * v4.y;
                O[k][2] += p * v4.z;
                O[k][3] += p * v4.w;
            }
        }
        __syncthreads();
    }

    float inv = 1.f / l;
    #pragma unroll
    for (int k = 0; k < 8; ++k) {
        float4 o4 = make_float4(O[k][0] * inv, O[k][1] * inv,
                                O[k][2] * inv, O[k][3] * inv);
        *(float4*)&g_y[qi * C_EMB + h * HD + c * 4 + k * 16] = o4;
    }
}

// ---------------------------------------------------------------------------
extern "C" void kernel_launch(void* const* d_in, const int* in_sizes, int n_in,
                              void* d_out, int out_size)
{
    const float* x    = (const float*)d_in[0];
    const float* ve   = (const float*)d_in[1];
    const float* cosb = (const float*)d_in[2];
    const float* sinb = (const float*)d_in[3];
    const float* wq   = (const float*)d_in[4];
    const float* wk   = (const float*)d_in[5];
    const float* wv   = (const float*)d_in[6];
    const float* wg   = (const float*)d_in[7];
    const float* wp   = (const float*)d_in[8];
    const int*   win  = (const int*)d_in[9];
    float* out = (float*)d_out;

    float *q, *k, *v, *y;
    cudaGetSymbolAddress((void**)&q, g_q);
    cudaGetSymbolAddress((void**)&k, g_k);
    cudaGetSymbolAddress((void**)&v, g_v);
    cudaGetSymbolAddress((void**)&y, g_y);

    dim3 gg(C_EMB / 128, T_SEQ / 128);
    gemm_tf32_kernel<<<gg, 256>>>(x, wq, q, T_SEQ, C_EMB, C_EMB);
    gemm_tf32_kernel<<<gg, 256>>>(x, wk, k, T_SEQ, C_EMB, C_EMB);
    gemm_tf32_kernel<<<gg, 256>>>(x, wv, v, T_SEQ, C_EMB, C_EMB);

    gate_ve_kernel<<<T_SEQ, 256>>>(x, ve, wg);
    rope_norm_kernel<<<dim3(T_SEQ, NH, 2), 64>>>(cosb, sinb);

    cudaFuncSetAttribute(attn_kernel,
                         cudaFuncAttributeMaxDynamicSharedMemorySize, ATTN_SMEM);
    attn_kernel<<<dim3(T_SEQ / 64, NH), 256, ATTN_SMEM>>>(win);

    gemm_tf32_kernel<<<gg, 256>>>(y, wp, out, T_SEQ, C_EMB, C_EMB);
}

// round 4
// speedup vs baseline: 3.7330x; 2.6471x over previous
#include <cuda_runtime.h>
#include <cuda_bf16.h>
#include <cstdint>

#define T_SEQ 4096
#define C_EMB 1024
#define NH 8
#define HD 128
#define HALF 64

// Scratch (device globals: allocation-free per harness rules)
__device__ float g_q[T_SEQ * C_EMB];
__device__ float g_k[T_SEQ * C_EMB];
__device__ float g_v[T_SEQ * C_EMB];
__device__ float g_y[T_SEQ * C_EMB];

__device__ __forceinline__ uint32_t f2tf(float x) {
    uint32_t r;
    asm("cvt.rna.tf32.f32 %0, %1;" : "=r"(r) : "f"(x));
    return r;
}

#define MMA_TF32(ACC, A0, A1, A2, A3, B0, B1)                              \
    asm volatile(                                                          \
        "mma.sync.aligned.m16n8k8.row.col.f32.tf32.tf32.f32 "              \
        "{%0,%1,%2,%3}, {%4,%5,%6,%7}, {%8,%9}, {%0,%1,%2,%3};"            \
        : "+f"((ACC)[0]), "+f"((ACC)[1]), "+f"((ACC)[2]), "+f"((ACC)[3])   \
        : "r"(A0), "r"(A1), "r"(A2), "r"(A3), "r"(B0), "r"(B1))

// ---------------------------------------------------------------------------
// TF32 tensor-core GEMM: C[M,N] = A[M,K] @ B[K,N], fp32 in/out.
// BM=BN=128, BK=16, 256 threads = 8 warps (2x4), warp tile 64x32.
// ---------------------------------------------------------------------------
#define AS_STRIDE 20
#define BS_STRIDE 136

__global__ __launch_bounds__(256) void gemm_tf32_kernel(
    const float* __restrict__ A, const float* __restrict__ B,
    float* __restrict__ C, int M, int N, int K)
{
    __shared__ uint32_t As[128 * AS_STRIDE];
    __shared__ uint32_t Bs[16 * BS_STRIDE];

    int tid = threadIdx.x;
    int lane = tid & 31, warp = tid >> 5;
    int wm = (warp >> 2) * 64;
    int wn = (warp & 3) * 32;
    int bm = blockIdx.y * 128, bn = blockIdx.x * 128;

    float acc[4][4][4];
    #pragma unroll
    for (int mt = 0; mt < 4; ++mt)
        #pragma unroll
        for (int nt = 0; nt < 4; ++nt)
            #pragma unroll
            for (int i = 0; i < 4; ++i) acc[mt][nt][i] = 0.f;

    for (int k0 = 0; k0 < K; k0 += 16) {
        #pragma unroll
        for (int j = 0; j < 2; ++j) {
            int i = tid + j * 256;
            int r = i >> 2, c4 = (i & 3) << 2;
            float4 v = *(const float4*)&A[(bm + r) * K + k0 + c4];
            uint4 u = make_uint4(f2tf(v.x), f2tf(v.y), f2tf(v.z), f2tf(v.w));
            *(uint4*)&As[r * AS_STRIDE + c4] = u;
        }
        #pragma unroll
        for (int j = 0; j < 2; ++j) {
            int i = tid + j * 256;
            int r = i >> 5, c4 = (i & 31) << 2;
            float4 v = *(const float4*)&B[(k0 + r) * N + bn + c4];
            uint4 u = make_uint4(f2tf(v.x), f2tf(v.y), f2tf(v.z), f2tf(v.w));
            *(uint4*)&Bs[r * BS_STRIDE + c4] = u;
        }
        __syncthreads();

        #pragma unroll
        for (int ks = 0; ks < 2; ++ks) {
            int kb = ks * 8;
            uint32_t af[4][4];
            #pragma unroll
            for (int mt = 0; mt < 4; ++mt) {
                int r0 = wm + mt * 16 + (lane >> 2);
                int c0 = kb + (lane & 3);
                af[mt][0] = As[r0 * AS_STRIDE + c0];
                af[mt][1] = As[(r0 + 8) * AS_STRIDE + c0];
                af[mt][2] = As[r0 * AS_STRIDE + c0 + 4];
                af[mt][3] = As[(r0 + 8) * AS_STRIDE + c0 + 4];
            }
            uint32_t bf[4][2];
            #pragma unroll
            for (int nt = 0; nt < 4; ++nt) {
                int rr = kb + (lane & 3);
                int cc = wn + nt * 8 + (lane >> 2);
                bf[nt][0] = Bs[rr * BS_STRIDE + cc];
                bf[nt][1] = Bs[(rr + 4) * BS_STRIDE + cc];
            }
            #pragma unroll
            for (int mt = 0; mt < 4; ++mt)
                #pragma unroll
                for (int nt = 0; nt < 4; ++nt)
                    MMA_TF32(acc[mt][nt], af[mt][0], af[mt][1], af[mt][2],
                             af[mt][3], bf[nt][0], bf[nt][1]);
        }
        __syncthreads();
    }

    #pragma unroll
    for (int mt = 0; mt < 4; ++mt) {
        int row = bm + wm + mt * 16 + (lane >> 2);
        #pragma unroll
        for (int nt = 0; nt < 4; ++nt) {
            int col = bn + wn + nt * 8 + ((lane & 3) << 1);
            *(float2*)&C[row * N + col] =
                make_float2(acc[mt][nt][0], acc[mt][nt][1]);
            *(float2*)&C[(row + 8) * N + col] =
                make_float2(acc[mt][nt][2], acc[mt][nt][3]);
        }
    }
}

// ---------------------------------------------------------------------------
// v += 2*sigmoid(x[:, :32] @ w_gate)[h] * ve     (one block per token)
// ---------------------------------------------------------------------------
__global__ __launch_bounds__(256) void gate_ve_kernel(
    const float* __restrict__ x, const float* __restrict__ ve,
    const float* __restrict__ w_gate)
{
    int t = blockIdx.x;
    __shared__ float xs[32];
    __shared__ float gate[NH];
    int tid = threadIdx.x;
    if (tid < 32) xs[tid] = x[t * C_EMB + tid];
    __syncthreads();
    if (tid < NH) {
        float s = 0.f;
        #pragma unroll
        for (int c = 0; c < 32; ++c) s += xs[c] * w_gate[c * NH + tid];
        gate[tid] = 2.f / (1.f + __expf(-s));
    }
    __syncthreads();
    for (int i = tid; i < C_EMB; i += 256)
        g_v[t * C_EMB + i] += gate[i >> 7] * ve[t * C_EMB + i];
}

// ---------------------------------------------------------------------------
// RoPE + RMSnorm on q (z=0) and k (z=1). One 64-thread block per (token, head).
// ---------------------------------------------------------------------------
__global__ __launch_bounds__(64) void rope_norm_kernel(
    const float* __restrict__ cosb, const float* __restrict__ sinb)
{
    float* buf = (blockIdx.z == 0) ? g_q : g_k;
    int t = blockIdx.x, h = blockIdx.y;
    int d = threadIdx.x;
    float* p = buf + t * C_EMB + h * HD;

    float x1 = p[d], x2 = p[d + HALF];
    float cs = cosb[t * HALF + d], sn = sinb[t * HALF + d];
    float y1 = x1 * cs + x2 * sn;
    float y2 = -x1 * sn + x2 * cs;

    float ss = y1 * y1 + y2 * y2;
    #pragma unroll
    for (int o = 16; o; o >>= 1) ss += __shfl_xor_sync(0xffffffffu, ss, o);
    __shared__ float w2[2];
    if ((d & 31) == 0) w2[d >> 5] = ss;
    __syncthreads();
    float tot = w2[0] + w2[1];
    float r = rsqrtf(tot * (1.f / HD) + 1e-6f);
    p[d] = y1 * r;
    p[d + HALF] = y2 * r;
}

// ---------------------------------------------------------------------------
// Tensor-core windowed flash attention (TF32 MMA, fp32 accum).
// Block = 128 queries x 1 head, 256 threads / 8 warps (warp = 16 q rows).
// Key tiles of 64. S = Q@K^T via mma, online softmax on fragments,
// P -> smem (warp-private rows, tf32), O += P@V via mma.
// Strides: Q/K 132 (=4 mod 32), V 136 (=8 mod 32), P 68 (=4 mod 32):
// all fragment LDS patterns bank-conflict-free.
// ---------------------------------------------------------------------------
#define BQ 128
#define BK 64
#define QS2 132
#define KS2 132
#define VS2 136
#define PS2 68
#define ATTN_SMEM ((BQ * QS2 + BK * KS2 + BK * VS2 + BQ * PS2) * 4)

__global__ __launch_bounds__(256) void attn_mma_kernel(const int* __restrict__ winp)
{
    extern __shared__ uint32_t smw[];
    uint32_t* Qs = smw;                 // 128 x 132
    uint32_t* Ks = Qs + BQ * QS2;       // 64 x 132
    uint32_t* Vs = Ks + BK * KS2;       // 64 x 136
    uint32_t* Ps = Vs + BK * VS2;       // 128 x 68

    int W = *winp;
    int q0 = blockIdx.x * BQ;
    int h = blockIdx.y;
    int tid = threadIdx.x, lane = tid & 31, warp = tid >> 5;
    int wm = warp * 16;
    int qr = lane >> 2, qc = lane & 3;
    const float scale = 0.08838834764831845f; // 1/sqrt(128)

    // Load Q tile (convert to tf32)
    for (int i = tid; i < BQ * 32; i += 256) {
        int r = i >> 5, c4 = (i & 31) << 2;
        float4 v = *(const float4*)&g_q[(q0 + r) * C_EMB + h * HD + c4];
        uint4 u = make_uint4(f2tf(v.x), f2tf(v.y), f2tf(v.z), f2tf(v.w));
        *(uint4*)&Qs[r * QS2 + c4] = u;
    }

    float O[16][4];
    #pragma unroll
    for (int nt = 0; nt < 16; ++nt)
        #pragma unroll
        for (int i = 0; i < 4; ++i) O[nt][i] = 0.f;
    float m1 = -1e30f, m2 = -1e30f, l1 = 0.f, l2 = 0.f;

    int r1 = q0 + wm + qr, r2 = r1 + 8;

    int lo = q0 - W + 1; if (lo < 0) lo = 0;
    int kt0 = lo >> 6;
    int kt1 = (q0 + BQ - 1) >> 6;

    for (int kt = kt0; kt <= kt1; ++kt) {
        int kbase = kt * BK;

        // Load K/V tiles (convert to tf32)
        for (int i = tid; i < BK * 32; i += 256) {
            int r = i >> 5, c4 = (i & 31) << 2;
            const float* kp = &g_k[(kbase + r) * C_EMB + h * HD + c4];
            const float* vp = &g_v[(kbase + r) * C_EMB + h * HD + c4];
            float4 kv = *(const float4*)kp;
            float4 vv = *(const float4*)vp;
            *(uint4*)&Ks[r * KS2 + c4] =
                make_uint4(f2tf(kv.x), f2tf(kv.y), f2tf(kv.z), f2tf(kv.w));
            *(uint4*)&Vs[r * VS2 + c4] =
                make_uint4(f2tf(vv.x), f2tf(vv.y), f2tf(vv.z), f2tf(vv.w));
        }
        __syncthreads();

        // S = Q @ K^T  (16 k-steps of 8, 8 n-tiles of 8 keys)
        float s[8][4];
        #pragma unroll
        for (int nt = 0; nt < 8; ++nt)
            #pragma unroll
            for (int i = 0; i < 4; ++i) s[nt][i] = 0.f;

        #pragma unroll
        for (int ks = 0; ks < 16; ++ks) {
            int ab = (wm + qr) * QS2 + ks * 8 + qc;
            uint32_t a0 = Qs[ab], a1 = Qs[ab + 8 * QS2];
            uint32_t a2 = Qs[ab + 4], a3 = Qs[ab + 8 * QS2 + 4];
            #pragma unroll
            for (int nt = 0; nt < 8; ++nt) {
                int bb = (nt * 8 + qr) * KS2 + ks * 8 + qc;
                MMA_TF32(s[nt], a0, a1, a2, a3, Ks[bb], Ks[bb + 4]);
            }
        }

        // Mask + scale + row max (rows r1, r2; cols 2 per reg pair)
        float mx1 = -1e30f, mx2 = -1e30f;
        #pragma unroll
        for (int nt = 0; nt < 8; ++nt) {
            int c0 = kbase + nt * 8 + qc * 2;
            int c1 = c0 + 1;
            s[nt][0] = ((c0 <= r1) && (r1 - c0 < W)) ? s[nt][0] * scale : -1e30f;
            s[nt][1] = ((c1 <= r1) && (r1 - c1 < W)) ? s[nt][1] * scale : -1e30f;
            s[nt][2] = ((c0 <= r2) && (r2 - c0 < W)) ? s[nt][2] * scale : -1e30f;
            s[nt][3] = ((c1 <= r2) && (r2 - c1 < W)) ? s[nt][3] * scale : -1e30f;
            mx1 = fmaxf(mx1, fmaxf(s[nt][0], s[nt][1]));
            mx2 = fmaxf(mx2, fmaxf(s[nt][2], s[nt][3]));
        }
        mx1 = fmaxf(mx1, __shfl_xor_sync(0xffffffffu, mx1, 1));
        mx1 = fmaxf(mx1, __shfl_xor_sync(0xffffffffu, mx1, 2));
        mx2 = fmaxf(mx2, __shfl_xor_sync(0xffffffffu, mx2, 1));
        mx2 = fmaxf(mx2, __shfl_xor_sync(0xffffffffu, mx2, 2));

        float mn1 = fmaxf(m1, mx1), mn2 = fmaxf(m2, mx2);
        float al1 = __expf(m1 - mn1), al2 = __expf(m2 - mn2);
        m1 = mn1; m2 = mn2;

        float ls1 = 0.f, ls2 = 0.f;
        int pr1 = (wm + qr) * PS2 + qc * 2;
        int pr2 = pr1 + 8 * PS2;
        #pragma unroll
        for (int nt = 0; nt < 8; ++nt) {
            float p0 = __expf(s[nt][0] - mn1);
            float p1 = __expf(s[nt][1] - mn1);
            float p2 = __expf(s[nt][2] - mn2);
            float p3 = __expf(s[nt][3] - mn2);
            ls1 += p0 + p1;
            ls2 += p2 + p3;
            *(uint2*)&Ps[pr1 + nt * 8] = make_uint2(f2tf(p0), f2tf(p1));
            *(uint2*)&Ps[pr2 + nt * 8] = make_uint2(f2tf(p2), f2tf(p3));
        }
        ls1 += __shfl_xor_sync(0xffffffffu, ls1, 1);
        ls1 += __shfl_xor_sync(0xffffffffu, ls1, 2);
        ls2 += __shfl_xor_sync(0xffffffffu, ls2, 1);
        ls2 += __shfl_xor_sync(0xffffffffu, ls2, 2);
        l1 = l1 * al1 + ls1;
        l2 = l2 * al2 + ls2;

        #pragma unroll
        for (int nt = 0; nt < 16; ++nt) {
            O[nt][0] *= al1; O[nt][1] *= al1;
            O[nt][2] *= al2; O[nt][3] *= al2;
        }
        __syncwarp();   // P rows are warp-private: stores -> loads visibility

        // O += P @ V  (8 k-steps over keys, 16 n-tiles over dims)
        #pragma unroll
        for (int ks = 0; ks < 8; ++ks) {
            int pb = (wm + qr) * PS2 + ks * 8 + qc;
            uint32_t a0 = Ps[pb], a1 = Ps[pb + 8 * PS2];
            uint32_t a2 = Ps[pb + 4], a3 = Ps[pb + 8 * PS2 + 4];
            #pragma unroll
            for (int nt = 0; nt < 16; ++nt) {
                int vb = (ks * 8 + qc) * VS2 + nt * 8 + qr;
                MMA_TF32(O[nt], a0, a1, a2, a3, Vs[vb], Vs[vb + 4 * VS2]);
            }
        }
        __syncthreads();   // before next tile overwrites Ks/Vs
    }

    float inv1 = 1.f / l1, inv2 = 1.f / l2;
    #pragma unroll
    for (int nt = 0; nt < 16; ++nt) {
        int col = h * HD + nt * 8 + qc * 2;
        *(float2*)&g_y[r1 * C_EMB + col] =
            make_float2(O[nt][0] * inv1, O[nt][1] * inv1);
        *(float2*)&g_y[r2 * C_EMB + col] =
            make_float2(O[nt][2] * inv2, O[nt][3] * inv2);
    }
}

// ---------------------------------------------------------------------------
extern "C" void kernel_launch(void* const* d_in, const int* in_sizes, int n_in,
                              void* d_out, int out_size)
{
    const float* x    = (const float*)d_in[0];
    const float* ve   = (const float*)d_in[1];
    const float* cosb = (const float*)d_in[2];
    const float* sinb = (const float*)d_in[3];
    const float* wq   = (const float*)d_in[4];
    const float* wk   = (const float*)d_in[5];
    const float* wv   = (const float*)d_in[6];
    const float* wg   = (const float*)d_in[7];
    const float* wp   = (const float*)d_in[8];
    const int*   win  = (const int*)d_in[9];
    float* out = (float*)d_out;

    float *q, *k, *v, *y;
    cudaGetSymbolAddress((void**)&q, g_q);
    cudaGetSymbolAddress((void**)&k, g_k);
    cudaGetSymbolAddress((void**)&v, g_v);
    cudaGetSymbolAddress((void**)&y, g_y);

    dim3 gg(C_EMB / 128, T_SEQ / 128);
    gemm_tf32_kernel<<<gg, 256>>>(x, wq, q, T_SEQ, C_EMB, C_EMB);
    gemm_tf32_kernel<<<gg, 256>>>(x, wk, k, T_SEQ, C_EMB, C_EMB);
    gemm_tf32_kernel<<<gg, 256>>>(x, wv, v, T_SEQ, C_EMB, C_EMB);

    gate_ve_kernel<<<T_SEQ, 256>>>(x, ve, wg);
    rope_norm_kernel<<<dim3(T_SEQ, NH, 2), 64>>>(cosb, sinb);

    cudaFuncSetAttribute(attn_mma_kernel,
                         cudaFuncAttributeMaxDynamicSharedMemorySize, ATTN_SMEM);
    attn_mma_kernel<<<dim3(T_SEQ / BQ, NH), 256, ATTN_SMEM>>>(win);

    gemm_tf32_kernel<<<gg, 256>>>(y, wp, out, T_SEQ, C_EMB, C_EMB);
}

// round 5
// speedup vs baseline: 3.7778x; 1.0120x over previous
#include <cuda_runtime.h>
#include <cuda_bf16.h>
#include <cstdint>

#define T_SEQ 4096
#define C_EMB 1024
#define NH 8
#define HD 128
#define HALF 64

// Scratch (device globals: allocation-free per harness rules)
__device__ float g_q[T_SEQ * C_EMB];
__device__ float g_k[T_SEQ * C_EMB];
__device__ float g_v[T_SEQ * C_EMB];
__device__ float g_y[T_SEQ * C_EMB];

__device__ __forceinline__ uint32_t f2tf(float x) {
    uint32_t r;
    asm("cvt.rna.tf32.f32 %0, %1;" : "=r"(r) : "f"(x));
    return r;
}

#define MMA_TF32(ACC, A0, A1, A2, A3, B0, B1)                              \
    asm volatile(                                                          \
        "mma.sync.aligned.m16n8k8.row.col.f32.tf32.tf32.f32 "              \
        "{%0,%1,%2,%3}, {%4,%5,%6,%7}, {%8,%9}, {%0,%1,%2,%3};"            \
        : "+f"((ACC)[0]), "+f"((ACC)[1]), "+f"((ACC)[2]), "+f"((ACC)[3])   \
        : "r"(A0), "r"(A1), "r"(A2), "r"(A3), "r"(B0), "r"(B1))

__device__ __forceinline__ void cp_async16(void* smem, const void* gmem) {
    uint32_t s = (uint32_t)__cvta_generic_to_shared(smem);
    asm volatile("cp.async.ca.shared.global [%0], [%1], 16;" :: "r"(s), "l"(gmem));
}
#define CP_COMMIT() asm volatile("cp.async.commit_group;")
#define CP_WAIT0()  asm volatile("cp.async.wait_group 0;")

// ---------------------------------------------------------------------------
// TF32 tensor-core GEMM, cp.async double-buffered.
// C[M,N] = A[M,K] @ B[K,N], fp32 in/out, tf32 cvt at fragment load.
// BM=BN=128, BK=16, 256 threads = 8 warps, warp tile 64x32.
// blockIdx.z selects (B,C) pair -> q/k/v fused in one launch.
// ---------------------------------------------------------------------------
#define AS_STRIDE 20
#define BS_STRIDE 136

__global__ __launch_bounds__(256) void gemm_tf32_kernel(
    const float* __restrict__ A,
    const float* __restrict__ Bp0, const float* __restrict__ Bp1,
    const float* __restrict__ Bp2,
    float* __restrict__ Cp0, float* __restrict__ Cp1, float* __restrict__ Cp2,
    int M, int N, int K)
{
    const float* B = (blockIdx.z == 0) ? Bp0 : (blockIdx.z == 1 ? Bp1 : Bp2);
    float*       C = (blockIdx.z == 0) ? Cp0 : (blockIdx.z == 1 ? Cp1 : Cp2);

    __shared__ float As[2][128 * AS_STRIDE];
    __shared__ float Bs[2][16 * BS_STRIDE];

    int tid = threadIdx.x;
    int lane = tid & 31, warp = tid >> 5;
    int wm = (warp >> 2) * 64;
    int wn = (warp & 3) * 32;
    int bm = blockIdx.y * 128, bn = blockIdx.x * 128;

    float acc[4][4][4];
    #pragma unroll
    for (int mt = 0; mt < 4; ++mt)
        #pragma unroll
        for (int nt = 0; nt < 4; ++nt)
            #pragma unroll
            for (int i = 0; i < 4; ++i) acc[mt][nt][i] = 0.f;

    // per-thread load coords
    int ar = tid >> 2, ac = (tid & 3) << 2;         // A: 128x16, 1 float4 + second at +64 rows? no: 2 strided
    int br = tid >> 5, bc = (tid & 31) << 2;        // B: 16x128

    auto issue = [&](int it, int buf) {
        int k0 = it * 16;
        // A tile 128x16: 512 float4, 2 per thread (i and i+256)
        #pragma unroll
        for (int j = 0; j < 2; ++j) {
            int i = tid + j * 256;
            int r = i >> 2, c4 = (i & 3) << 2;
            cp_async16(&As[buf][r * AS_STRIDE + c4], &A[(bm + r) * K + k0 + c4]);
        }
        // B tile 16x128: 512 float4, 2 per thread
        #pragma unroll
        for (int j = 0; j < 2; ++j) {
            int i = tid + j * 256;
            int r = i >> 5, c4 = (i & 31) << 2;
            cp_async16(&Bs[buf][r * BS_STRIDE + c4], &B[(k0 + r) * N + bn + c4]);
        }
        CP_COMMIT();
    };

    (void)ar; (void)ac; (void)br; (void)bc;

    const int nIter = K / 16;
    issue(0, 0);
    CP_WAIT0();
    __syncthreads();

    for (int it = 0; it < nIter; ++it) {
        int cur = it & 1;
        if (it + 1 < nIter) issue(it + 1, cur ^ 1);

        const float* Ab = As[cur];
        const float* Bb = Bs[cur];
        #pragma unroll
        for (int ks = 0; ks < 2; ++ks) {
            int kb = ks * 8;
            uint32_t af[4][4];
            #pragma unroll
            for (int mt = 0; mt < 4; ++mt) {
                int r0 = wm + mt * 16 + (lane >> 2);
                int c0 = kb + (lane & 3);
                af[mt][0] = f2tf(Ab[r0 * AS_STRIDE + c0]);
                af[mt][1] = f2tf(Ab[(r0 + 8) * AS_STRIDE + c0]);
                af[mt][2] = f2tf(Ab[r0 * AS_STRIDE + c0 + 4]);
                af[mt][3] = f2tf(Ab[(r0 + 8) * AS_STRIDE + c0 + 4]);
            }
            uint32_t bf[4][2];
            #pragma unroll
            for (int nt = 0; nt < 4; ++nt) {
                int rr = kb + (lane & 3);
                int cc = wn + nt * 8 + (lane >> 2);
                bf[nt][0] = f2tf(Bb[rr * BS_STRIDE + cc]);
                bf[nt][1] = f2tf(Bb[(rr + 4) * BS_STRIDE + cc]);
            }
            #pragma unroll
            for (int mt = 0; mt < 4; ++mt)
                #pragma unroll
                for (int nt = 0; nt < 4; ++nt)
                    MMA_TF32(acc[mt][nt], af[mt][0], af[mt][1], af[mt][2],
                             af[mt][3], bf[nt][0], bf[nt][1]);
        }

        if (it + 1 < nIter) {
            CP_WAIT0();
            __syncthreads();
        }
    }

    #pragma unroll
    for (int mt = 0; mt < 4; ++mt) {
        int row = bm + wm + mt * 16 + (lane >> 2);
        #pragma unroll
        for (int nt = 0; nt < 4; ++nt) {
            int col = bn + wn + nt * 8 + ((lane & 3) << 1);
            *(float2*)&C[row * N + col] =
                make_float2(acc[mt][nt][0], acc[mt][nt][1]);
            *(float2*)&C[(row + 8) * N + col] =
                make_float2(acc[mt][nt][2], acc[mt][nt][3]);
        }
    }
}

// ---------------------------------------------------------------------------
// v += 2*sigmoid(x[:, :32] @ w_gate)[h] * ve     (one block per token)
// ---------------------------------------------------------------------------
__global__ __launch_bounds__(256) void gate_ve_kernel(
    const float* __restrict__ x, const float* __restrict__ ve,
    const float* __restrict__ w_gate)
{
    int t = blockIdx.x;
    __shared__ float xs[32];
    __shared__ float gate[NH];
    int tid = threadIdx.x;
    if (tid < 32) xs[tid] = x[t * C_EMB + tid];
    __syncthreads();
    if (tid < NH) {
        float s = 0.f;
        #pragma unroll
        for (int c = 0; c < 32; ++c) s += xs[c] * w_gate[c * NH + tid];
        gate[tid] = 2.f / (1.f + __expf(-s));
    }
    __syncthreads();
    for (int i = tid; i < C_EMB; i += 256)
        g_v[t * C_EMB + i] += gate[i >> 7] * ve[t * C_EMB + i];
}

// ---------------------------------------------------------------------------
// RoPE + RMSnorm on q (z=0) and k (z=1). One 64-thread block per (token, head).
// ---------------------------------------------------------------------------
__global__ __launch_bounds__(64) void rope_norm_kernel(
    const float* __restrict__ cosb, const float* __restrict__ sinb)
{
    float* buf = (blockIdx.z == 0) ? g_q : g_k;
    int t = blockIdx.x, h = blockIdx.y;
    int d = threadIdx.x;
    float* p = buf + t * C_EMB + h * HD;

    float x1 = p[d], x2 = p[d + HALF];
    float cs = cosb[t * HALF + d], sn = sinb[t * HALF + d];
    float y1 = x1 * cs + x2 * sn;
    float y2 = -x1 * sn + x2 * cs;

    float ss = y1 * y1 + y2 * y2;
    #pragma unroll
    for (int o = 16; o; o >>= 1) ss += __shfl_xor_sync(0xffffffffu, ss, o);
    __shared__ float w2[2];
    if ((d & 31) == 0) w2[d >> 5] = ss;
    __syncthreads();
    float tot = w2[0] + w2[1];
    float r = rsqrtf(tot * (1.f / HD) + 1e-6f);
    p[d] = y1 * r;
    p[d + HALF] = y2 * r;
}

// ---------------------------------------------------------------------------
// Tensor-core windowed flash attention (TF32 MMA, fp32 accum).
// Block = 128 queries x 1 head, 256 threads / 8 warps (warp = 16 q rows).
// ---------------------------------------------------------------------------
#define BQ 128
#define BK 64
#define QS2 132
#define KS2 132
#define VS2 136
#define PS2 68
#define ATTN_SMEM ((BQ * QS2 + BK * KS2 + BK * VS2 + BQ * PS2) * 4)

__global__ __launch_bounds__(256) void attn_mma_kernel(const int* __restrict__ winp)
{
    extern __shared__ uint32_t smw[];
    uint32_t* Qs = smw;                 // 128 x 132
    uint32_t* Ks = Qs + BQ * QS2;       // 64 x 132
    uint32_t* Vs = Ks + BK * KS2;       // 64 x 136
    uint32_t* Ps = Vs + BK * VS2;       // 128 x 68

    int W = *winp;
    int q0 = blockIdx.x * BQ;
    int h = blockIdx.y;
    int tid = threadIdx.x, lane = tid & 31, warp = tid >> 5;
    int wm = warp * 16;
    int qr = lane >> 2, qc = lane & 3;
    const float scale = 0.08838834764831845f; // 1/sqrt(128)

    for (int i = tid; i < BQ * 32; i += 256) {
        int r = i >> 5, c4 = (i & 31) << 2;
        float4 v = *(const float4*)&g_q[(q0 + r) * C_EMB + h * HD + c4];
        uint4 u = make_uint4(f2tf(v.x), f2tf(v.y), f2tf(v.z), f2tf(v.w));
        *(uint4*)&Qs[r * QS2 + c4] = u;
    }

    float O[16][4];
    #pragma unroll
    for (int nt = 0; nt < 16; ++nt)
        #pragma unroll
        for (int i = 0; i < 4; ++i) O[nt][i] = 0.f;
    float m1 = -1e30f, m2 = -1e30f, l1 = 0.f, l2 = 0.f;

    int r1 = q0 + wm + qr, r2 = r1 + 8;

    int lo = q0 - W + 1; if (lo < 0) lo = 0;
    int kt0 = lo >> 6;
    int kt1 = (q0 + BQ - 1) >> 6;

    for (int kt = kt0; kt <= kt1; ++kt) {
        int kbase = kt * BK;

        for (int i = tid; i < BK * 32; i += 256) {
            int r = i >> 5, c4 = (i & 31) << 2;
            float4 kv = *(const float4*)&g_k[(kbase + r) * C_EMB + h * HD + c4];
            float4 vv = *(const float4*)&g_v[(kbase + r) * C_EMB + h * HD + c4];
            *(uint4*)&Ks[r * KS2 + c4] =
                make_uint4(f2tf(kv.x), f2tf(kv.y), f2tf(kv.z), f2tf(kv.w));
            *(uint4*)&Vs[r * VS2 + c4] =
                make_uint4(f2tf(vv.x), f2tf(vv.y), f2tf(vv.z), f2tf(vv.w));
        }
        __syncthreads();

        float s[8][4];
        #pragma unroll
        for (int nt = 0; nt < 8; ++nt)
            #pragma unroll
            for (int i = 0; i < 4; ++i) s[nt][i] = 0.f;

        #pragma unroll
        for (int ks = 0; ks < 16; ++ks) {
            int ab = (wm + qr) * QS2 + ks * 8 + qc;
            uint32_t a0 = Qs[ab], a1 = Qs[ab + 8 * QS2];
            uint32_t a2 = Qs[ab + 4], a3 = Qs[ab + 8 * QS2 + 4];
            #pragma unroll
            for (int nt = 0; nt < 8; ++nt) {
                int bb = (nt * 8 + qr) * KS2 + ks * 8 + qc;
                MMA_TF32(s[nt], a0, a1, a2, a3, Ks[bb], Ks[bb + 4]);
            }
        }

        float mx1 = -1e30f, mx2 = -1e30f;
        #pragma unroll
        for (int nt = 0; nt < 8; ++nt) {
            int c0 = kbase + nt * 8 + qc * 2;
            int c1 = c0 + 1;
            s[nt][0] = ((c0 <= r1) && (r1 - c0 < W)) ? s[nt][0] * scale : -1e30f;
            s[nt][1] = ((c1 <= r1) && (r1 - c1 < W)) ? s[nt][1] * scale : -1e30f;
            s[nt][2] = ((c0 <= r2) && (r2 - c0 < W)) ? s[nt][2] * scale : -1e30f;
            s[nt][3] = ((c1 <= r2) && (r2 - c1 < W)) ? s[nt][3] * scale : -1e30f;
            mx1 = fmaxf(mx1, fmaxf(s[nt][0], s[nt][1]));
            mx2 = fmaxf(mx2, fmaxf(s[nt][2], s[nt][3]));
        }
        mx1 = fmaxf(mx1, __shfl_xor_sync(0xffffffffu, mx1, 1));
        mx1 = fmaxf(mx1, __shfl_xor_sync(0xffffffffu, mx1, 2));
        mx2 = fmaxf(mx2, __shfl_xor_sync(0xffffffffu, mx2, 1));
        mx2 = fmaxf(mx2, __shfl_xor_sync(0xffffffffu, mx2, 2));

        float mn1 = fmaxf(m1, mx1), mn2 = fmaxf(m2, mx2);
        float al1 = __expf(m1 - mn1), al2 = __expf(m2 - mn2);
        m1 = mn1; m2 = mn2;

        float ls1 = 0.f, ls2 = 0.f;
        int pr1 = (wm + qr) * PS2 + qc * 2;
        int pr2 = pr1 + 8 * PS2;
        #pragma unroll
        for (int nt = 0; nt < 8; ++nt) {
            float p0 = __expf(s[nt][0] - mn1);
            float p1 = __expf(s[nt][1] - mn1);
            float p2 = __expf(s[nt][2] - mn2);
            float p3 = __expf(s[nt][3] - mn2);
            ls1 += p0 + p1;
            ls2 += p2 + p3;
            *(uint2*)&Ps[pr1 + nt * 8] = make_uint2(f2tf(p0), f2tf(p1));
            *(uint2*)&Ps[pr2 + nt * 8] = make_uint2(f2tf(p2), f2tf(p3));
        }
        ls1 += __shfl_xor_sync(0xffffffffu, ls1, 1);
        ls1 += __shfl_xor_sync(0xffffffffu, ls1, 2);
        ls2 += __shfl_xor_sync(0xffffffffu, ls2, 1);
        ls2 += __shfl_xor_sync(0xffffffffu, ls2, 2);
        l1 = l1 * al1 + ls1;
        l2 = l2 * al2 + ls2;

        #pragma unroll
        for (int nt = 0; nt < 16; ++nt) {
            O[nt][0] *= al1; O[nt][1] *= al1;
            O[nt][2] *= al2; O[nt][3] *= al2;
        }
        __syncwarp();

        #pragma unroll
        for (int ks = 0; ks < 8; ++ks) {
            int pb = (wm + qr) * PS2 + ks * 8 + qc;
            uint32_t a0 = Ps[pb], a1 = Ps[pb + 8 * PS2];
            uint32_t a2 = Ps[pb + 4], a3 = Ps[pb + 8 * PS2 + 4];
            #pragma unroll
            for (int nt = 0; nt < 16; ++nt) {
                int vb = (ks * 8 + qc) * VS2 + nt * 8 + qr;
                MMA_TF32(O[nt], a0, a1, a2, a3, Vs[vb], Vs[vb + 4 * VS2]);
            }
        }
        __syncthreads();
    }

    float inv1 = 1.f / l1, inv2 = 1.f / l2;
    #pragma unroll
    for (int nt = 0; nt < 16; ++nt) {
        int col = h * HD + nt * 8 + qc * 2;
        *(float2*)&g_y[r1 * C_EMB + col] =
            make_float2(O[nt][0] * inv1, O[nt][1] * inv1);
        *(float2*)&g_y[r2 * C_EMB + col] =
            make_float2(O[nt][2] * inv2, O[nt][3] * inv2);
    }
}

// ---------------------------------------------------------------------------
extern "C" void kernel_launch(void* const* d_in, const int* in_sizes, int n_in,
                              void* d_out, int out_size)
{
    const float* x    = (const float*)d_in[0];
    const float* ve   = (const float*)d_in[1];
    const float* cosb = (const float*)d_in[2];
    const float* sinb = (const float*)d_in[3];
    const float* wq   = (const float*)d_in[4];
    const float* wk   = (const float*)d_in[5];
    const float* wv   = (const float*)d_in[6];
    const float* wg   = (const float*)d_in[7];
    const float* wp   = (const float*)d_in[8];
    const int*   win  = (const int*)d_in[9];
    float* out = (float*)d_out;

    float *q, *k, *v, *y;
    cudaGetSymbolAddress((void**)&q, g_q);
    cudaGetSymbolAddress((void**)&k, g_k);
    cudaGetSymbolAddress((void**)&v, g_v);
    cudaGetSymbolAddress((void**)&y, g_y);

    // Fused q/k/v projections: one launch, blockIdx.z picks weight/output.
    dim3 gqkv(C_EMB / 128, T_SEQ / 128, 3);
    gemm_tf32_kernel<<<gqkv, 256>>>(x, wq, wk, wv, q, k, v,
                                    T_SEQ, C_EMB, C_EMB);

    gate_ve_kernel<<<T_SEQ, 256>>>(x, ve, wg);
    rope_norm_kernel<<<dim3(T_SEQ, NH, 2), 64>>>(cosb, sinb);

    cudaFuncSetAttribute(attn_mma_kernel,
                         cudaFuncAttributeMaxDynamicSharedMemorySize, ATTN_SMEM);
    attn_mma_kernel<<<dim3(T_SEQ / BQ, NH), 256, ATTN_SMEM>>>(win);

    dim3 gp(C_EMB / 128, T_SEQ / 128, 1);
    gemm_tf32_kernel<<<gp, 256>>>(y, wp, wp, wp, out, out, out,
                                  T_SEQ, C_EMB, C_EMB);
}